// round 2
// baseline (speedup 1.0000x reference)
#include <cuda_runtime.h>

#define BB 32
#define CC 64
#define HW 4096
#define KK 512
#define DD 64
#define NFLAT 131072            // BB*HH*WW
#define SD 68                   // padded shared row stride (floats)

// Output layout (concatenated tuple, fp32):
#define LOSS_OFF   0ULL
#define QOUT_OFF   1ULL          // 8,388,608  (NCHW)
#define PERP_OFF   8388609ULL
#define ENC_OFF    8388610ULL    // 67,108,864 (NFLAT x KK one-hot)
#define QFLAT_OFF  75497474ULL   // 8,388,608  (NFLAT x DD)

#define TAU_GAP  4e-3f           // trigger exact re-resolve
#define TAU_BAND 8e-3f           // candidate band inside re-resolve

__device__ double g_sse;
__device__ int    g_hist[KK];

__global__ void vq_init_kernel() {
    int t = threadIdx.x;
    if (t < KK) g_hist[t] = 0;
    if (t == 0) g_sse = 0.0;
}

extern __shared__ float smem[];  // [KK*SD] padded embedding + [KK] half-norms

__global__ __launch_bounds__(512, 1)
void vq_main_kernel(const float* __restrict__ in,
                    const float* __restrict__ emb,
                    float* __restrict__ out)
{
    float* se = smem;             // KK rows of SD floats (first DD valid)
    float* sh = smem + KK * SD;   // 0.5 * ||e_k||^2
    __shared__ int   shist[KK];
    __shared__ float s_sse;

    const int tid = threadIdx.x;

    // cooperative load of embedding into padded shared (float4 per row-chunk)
    for (int i = tid; i < KK * DD / 4; i += blockDim.x) {
        int k  = i >> 4;          // / (DD/4)
        int d4 = i & 15;
        reinterpret_cast<float4*>(se + k * SD)[d4] =
            reinterpret_cast<const float4*>(emb)[i];
    }
    for (int i = tid; i < KK; i += blockDim.x) shist[i] = 0;
    if (tid == 0) s_sse = 0.0f;
    __syncthreads();

    // half-norms: one k per thread (blockDim == KK)
    {
        const float* e = se + tid * SD;
        float s = 0.f;
        #pragma unroll
        for (int d = 0; d < DD; d++) s = fmaf(e[d], e[d], s);
        sh[tid] = 0.5f * s;
    }
    __syncthreads();

    const int n  = blockIdx.x * blockDim.x + tid;
    const int b  = n >> 12;       // / HW
    const int hw = n & 4095;

    // load query vector (coalesced across lanes for each c)
    float x[DD];
    const float* inb = in + (size_t)b * CC * HW + hw;
    #pragma unroll
    for (int c = 0; c < DD; c++) x[c] = __ldg(inb + (size_t)c * HW);

    // argmax over k of (x . e_k - 0.5*||e_k||^2)  == argmin distance.
    // strict '>' keeps FIRST max -> matches jnp.argmin first-min tiebreak.
    float best  = -3.402823466e38f;
    float best2 = -3.402823466e38f;
    int   bidx = 0;
    #pragma unroll 2
    for (int k = 0; k < KK; k++) {
        const float4* e4 = reinterpret_cast<const float4*>(se + k * SD);
        float a0 = 0.f, a1 = 0.f, a2 = 0.f, a3 = 0.f;
        #pragma unroll
        for (int d = 0; d < 16; d++) {
            float4 v = e4[d];               // warp-broadcast LDS.128
            a0 = fmaf(x[4*d+0], v.x, a0);
            a1 = fmaf(x[4*d+1], v.y, a1);
            a2 = fmaf(x[4*d+2], v.z, a2);
            a3 = fmaf(x[4*d+3], v.w, a3);
        }
        float score = (a0 + a1) + (a2 + a3) - sh[k];
        if (score > best) { best2 = best; best = score; bidx = k; }
        else if (score > best2) { best2 = score; }
    }

    // Near-tie: resolve the argmin EXACTLY (fp64 true distance) for all
    // candidates within the ambiguity band. Rare (~2e-3 of rows).
    if (best - best2 < TAU_GAP) {
        double bd = 1e300;
        int    bi = 0;
        const float cut = best - TAU_BAND;
        for (int k = 0; k < KK; k++) {
            const float4* e4 = reinterpret_cast<const float4*>(se + k * SD);
            float a0 = 0.f, a1 = 0.f, a2 = 0.f, a3 = 0.f;
            #pragma unroll
            for (int d = 0; d < 16; d++) {
                float4 v = e4[d];
                a0 = fmaf(x[4*d+0], v.x, a0);
                a1 = fmaf(x[4*d+1], v.y, a1);
                a2 = fmaf(x[4*d+2], v.z, a2);
                a3 = fmaf(x[4*d+3], v.w, a3);
            }
            float score = (a0 + a1) + (a2 + a3) - sh[k];
            if (score > cut) {
                const float* e = se + k * SD;
                double acc = 0.0;
                for (int d = 0; d < DD; d++) {
                    double df = (double)x[d] - (double)e[d];
                    acc = fma(df, df, acc);
                }
                if (acc < bd) { bd = acc; bi = k; }   // strict < keeps first k
            }
        }
        bidx = bi;
    }

    atomicAdd(&shist[bidx], 1);

    // epilogue: quantized outputs + sse, single pass over c
    const float* eb    = se + bidx * SD;
    float*       qout  = out + QOUT_OFF  + (size_t)b * CC * HW + hw;
    float*       qflat = out + QFLAT_OFF + (size_t)n * DD;     // 8B-aligned
    float sse = 0.f;
    float2 pair;
    #pragma unroll
    for (int c = 0; c < DD; c++) {
        float e = eb[c];
        float dff = x[c] - e;
        sse = fmaf(dff, dff, sse);
        qout[(size_t)c * HW] = e;                 // coalesced per c
        if (c & 1) { pair.y = e; reinterpret_cast<float2*>(qflat)[c >> 1] = pair; }
        else       { pair.x = e; }
    }

    // block-coalesced zero of this block's encodings slab (512 rows x 512 cols)
    {
        float2* ez = reinterpret_cast<float2*>(out + ENC_OFF +
                       (size_t)blockIdx.x * 512ULL * (size_t)KK);
        float2 z = make_float2(0.f, 0.f);
        const int total = 512 * KK / 2;
        for (int i = tid; i < total; i += blockDim.x) ez[i] = z;
    }
    __syncthreads();
    out[ENC_OFF + (size_t)n * KK + bidx] = 1.0f;

    // reductions
    #pragma unroll
    for (int off = 16; off; off >>= 1)
        sse += __shfl_xor_sync(0xFFFFFFFFu, sse, off);
    if ((tid & 31) == 0) atomicAdd(&s_sse, sse);
    __syncthreads();
    if (tid == 0) atomicAdd(&g_sse, (double)s_sse);
    for (int i = tid; i < KK; i += blockDim.x) {
        int h = shist[i];
        if (h) atomicAdd(&g_hist[i], h);
    }
}

__global__ __launch_bounds__(512)
void vq_finalize_kernel(float* __restrict__ out)
{
    __shared__ float red[512];
    int tid = threadIdx.x;
    float p = (float)g_hist[tid] / (float)NFLAT;
    red[tid] = p * logf(p + 1e-10f);
    __syncthreads();
    #pragma unroll
    for (int s = 256; s; s >>= 1) {
        if (tid < s) red[tid] += red[tid + s];
        __syncthreads();
    }
    if (tid == 0) {
        out[PERP_OFF] = expf(-red[0]);
        out[LOSS_OFF] = 0.25f * (float)(g_sse / ((double)NFLAT * (double)DD));
    }
}

extern "C" void kernel_launch(void* const* d_in, const int* in_sizes, int n_in,
                              void* d_out, int out_size)
{
    const float* in  = (const float*)d_in[0];
    const float* emb = (const float*)d_in[1];
    float* out = (float*)d_out;

    size_t smem_bytes = (size_t)(KK * SD + KK) * sizeof(float);  // ~138 KB
    cudaFuncSetAttribute(vq_main_kernel,
                         cudaFuncAttributeMaxDynamicSharedMemorySize,
                         (int)smem_bytes);

    vq_init_kernel<<<1, 512>>>();
    vq_main_kernel<<<NFLAT / 512, 512, smem_bytes>>>(in, emb, out);
    vq_finalize_kernel<<<1, 512>>>(out);
}